// round 8
// baseline (speedup 1.0000x reference)
#include <cuda_runtime.h>
#include <math.h>

#define H 512
#define W 512
#define HW (512*512)
#define NB 8          // batch
#define NIMG 16       // 8 pred + 8 true
#define NUM_ITER 40
#define BH 16
#define NBANDS (H/BH)   // 32
#define BIGF 3.0e38f

// ---- scratch (device globals; no allocation) ----
__device__ float g_imgA[(size_t)NIMG*HW];
__device__ float g_imgB[(size_t)NIMG*HW];
__device__ float g_skel[(size_t)NIMG*HW];
__device__ float g_dicePart[256*3];           // [block][inter,sumT,sumP]
__device__ float g_epPart[NIMG*NBANDS*3];     // [img][band][s,sy,sx]
__device__ int   g_prog[NIMG*NBANDS];         // monotonic per-band progress (never reset)

__device__ __forceinline__ float f3min(float a,float b,float c){return fminf(fminf(a,b),c);}
__device__ __forceinline__ float f3max(float a,float b,float c){return fmaxf(fmaxf(a,b),c);}

__device__ __forceinline__ int ld_acquire_gpu(const int* p) {
    int v;
    asm volatile("ld.acquire.gpu.b32 %0, [%1];" : "=r"(v) : "l"(p) : "memory");
    return v;
}
__device__ __forceinline__ void st_release_gpu(int* p, int v) {
    asm volatile("st.release.gpu.b32 [%0], %1;" :: "l"(p), "r"(v) : "memory");
}

// ---------------------------------------------------------------------------
// prep: prob = softmax(net)[:,1] = sigmoid(x1-x0); true->float; dice partials.
// ---------------------------------------------------------------------------
__global__ void prep_kernel(const float* __restrict__ net, const int* __restrict__ yt) {
    int tid = blockIdx.x * 256 + threadIdx.x;
    float inter = 0.f, st = 0.f, sp = 0.f;
    for (int idx = tid; idx < NB*HW; idx += 256*256) {
        int b = idx / HW;
        int p = idx - b*HW;
        float x0 = net[(size_t)b*2*HW + p];
        float x1 = net[(size_t)b*2*HW + HW + p];
        float prob = 1.f / (1.f + __expf(x0 - x1));
        float t = (float)yt[idx];
        g_imgA[(size_t)b*HW + p] = prob;
        g_imgA[(size_t)(NB + b)*HW + p] = t;
        inter += t * prob;
        st += t;
        sp += prob;
    }
    __shared__ float s[3][256];
    s[0][threadIdx.x] = inter; s[1][threadIdx.x] = st; s[2][threadIdx.x] = sp;
    __syncthreads();
    for (int off = 128; off > 0; off >>= 1) {
        if (threadIdx.x < off) {
            s[0][threadIdx.x] += s[0][threadIdx.x + off];
            s[1][threadIdx.x] += s[1][threadIdx.x + off];
            s[2][threadIdx.x] += s[2][threadIdx.x + off];
        }
        __syncthreads();
    }
    if (threadIdx.x == 0) {
        g_dicePart[blockIdx.x*3 + 0] = s[0][0];
        g_dicePart[blockIdx.x*3 + 1] = s[1][0];
        g_dicePart[blockIdx.x*3 + 2] = s[2][0];
    }
}

// ---------------------------------------------------------------------------
// INIT sweep: skel = relu(img - dilate3x3(erode(img))). (single launch, as R5)
// ---------------------------------------------------------------------------
__global__ __launch_bounds__(128) void sweep_init_kernel() {
    const int img = blockIdx.y;
    const int R0row = blockIdx.x * BH;
    const int lane = threadIdx.x & 31;
    const int colBase = ((threadIdx.x >> 5) << 7) + (lane << 2);
    const bool isL = (lane == 0), isR = (lane == 31);
    const bool edgeL = (colBase == 0), edgeR = (colBase == W-4);
    const float* __restrict__ in = g_imgA + (size_t)img*HW;
    float* __restrict__ skel = g_skel + (size_t)img*HW;

    const float4 PINF = make_float4(BIGF,BIGF,BIGF,BIGF);
    float4 i0=PINF, i1=PINF, L0=PINF, L1=PINF, Rv0=PINF, Rv1=PINF;
    float4 hp=PINF; float hpL1=BIGF, hpR0=BIGF;
    float4 e1a=make_float4(-BIGF,-BIGF,-BIGF,-BIGF), e1b=e1a;
    float e1aL=-BIGF, e1bL=-BIGF, e1aR=-BIGF, e1bR=-BIGF;

    const int rStart = R0row-2, rEnd = R0row+BH+1;   // BH+4 = 20 rows
    float4 nCur=PINF, nL=PINF, nR=PINF;
    if (rStart >= 0 && rStart < H) {
        const float* p = in + rStart*W + colBase;
        nCur = *(const float4*)p;
        if (isL && !edgeL) nL = *(const float4*)(p - 4);
        if (isR && !edgeR) nR = *(const float4*)(p + 4);
    }

    #pragma unroll 2
    for (int t = 0; t < BH+4; t++) {
        const int r = rStart + t;
        float4 cur = nCur, Lc = nL, Rc = nR;
        nCur = PINF; nL = PINF; nR = PINF;
        {
            int rn = r + 1;
            if (rn <= rEnd && (unsigned)rn < (unsigned)H) {
                const float* p = in + rn*W + colBase;
                nCur = *(const float4*)p;
                if (isL && !edgeL) nL = *(const float4*)(p - 4);
                if (isR && !edgeR) nR = *(const float4*)(p + 4);
            }
        }
        float xm1 = __shfl_up_sync(0xffffffffu, cur.w, 1); if (isL) xm1 = Lc.w;
        float xp1 = __shfl_down_sync(0xffffffffu, cur.x, 1); if (isR) xp1 = Rc.x;
        float4 hc;
        hc.x = f3min(xm1, cur.x, cur.y);
        hc.y = f3min(cur.x, cur.y, cur.z);
        hc.z = f3min(cur.y, cur.z, cur.w);
        hc.w = f3min(cur.z, cur.w, xp1);
        float hcL1 = f3min(Lc.z, Lc.w, cur.x);
        float hcR0 = f3min(cur.w, Rc.x, Rc.y);

        float4 e1n;
        e1n.x = fminf(f3min(i0.x,i1.x,cur.x), hp.x);
        e1n.y = fminf(f3min(i0.y,i1.y,cur.y), hp.y);
        e1n.z = fminf(f3min(i0.z,i1.z,cur.z), hp.z);
        e1n.w = fminf(f3min(i0.w,i1.w,cur.w), hp.w);
        float e1nL = fminf(f3min(L0.w,L1.w,Lc.w), hpL1);
        float e1nR = fminf(f3min(Rv0.x,Rv1.x,Rc.x), hpR0);
        {
            int k = r-1;
            if (k < 0 || k >= H) {
                e1n = make_float4(-BIGF,-BIGF,-BIGF,-BIGF);
                e1nL = e1nR = -BIGF;
            }
        }
        if (edgeL) e1nL = -BIGF;
        if (edgeR) e1nR = -BIGF;

        if (t >= 4) {   // r >= R0row+2
            float4 mv;
            mv.x = f3max(e1a.x, e1b.x, e1n.x);
            mv.y = f3max(e1a.y, e1b.y, e1n.y);
            mv.z = f3max(e1a.z, e1b.z, e1n.z);
            mv.w = f3max(e1a.w, e1b.w, e1n.w);
            float mvL = f3max(e1aL, e1bL, e1nL);
            float mvR = f3max(e1aR, e1bR, e1nR);
            float mm1 = __shfl_up_sync(0xffffffffu, mv.w, 1); if (isL) mm1 = mvL;
            float mp1 = __shfl_down_sync(0xffffffffu, mv.x, 1); if (isR) mp1 = mvR;
            float4 open;
            open.x = f3max(mm1, mv.x, mv.y);
            open.y = f3max(mv.x, mv.y, mv.z);
            open.z = f3max(mv.y, mv.z, mv.w);
            open.w = f3max(mv.z, mv.w, mp1);
            int k2 = r-2;
            float4 s;
            s.x = fmaxf(i0.x - open.x, 0.f);
            s.y = fmaxf(i0.y - open.y, 0.f);
            s.z = fmaxf(i0.z - open.z, 0.f);
            s.w = fmaxf(i0.w - open.w, 0.f);
            *(float4*)(skel + k2*W + colBase) = s;
        }
        i0=i1; i1=cur; L0=L1; L1=Lc; Rv0=Rv1; Rv1=Rc;
        hp=hc; hpL1=hcL1; hpR0=hcR0;
        e1a=e1b; e1b=e1n; e1aL=e1bL; e1bL=e1nL; e1aR=e1bR; e1bR=e1nR;
    }
}

// ---------------------------------------------------------------------------
// PERSISTENT STEP kernel: all NUM_ITER iterations in ONE launch.
// 512 blocks, all co-resident (<=128 regs enforced => 4 blocks/SM * 148 = 592).
// Band (blockIdx.x) of image (blockIdx.y); per-band monotonic progress counter.
// Before iteration i: wait neighbors' counters >= base+i (they finished i-1:
// their halo rows are produced AND they're done reading the buffer we write).
// After iteration i: threadfence + syncthreads + release-store base+i+1.
// Counters are never reset; every launch adds exactly NUM_ITER to each, so
// base re-read at entry makes graph replays self-consistent.
// Inner body identical to the proven R5 sweep (4 px/lane, shfl halos,
// 1-row prefetch, unroll 2).
// ---------------------------------------------------------------------------
__global__ __launch_bounds__(128, 4) void sweep_persist_kernel() {
    const int img = blockIdx.y;
    const int band = blockIdx.x;
    const int R0row = band * BH;
    const int lane = threadIdx.x & 31;
    const int colBase = ((threadIdx.x >> 5) << 7) + (lane << 2);
    const bool isL = (lane == 0), isR = (lane == 31);
    const bool edgeL = (colBase == 0), edgeR = (colBase == W-4);
    float* __restrict__ skel = g_skel + (size_t)img*HW;

    int* myProg = &g_prog[img*NBANDS + band];
    int* leftProg  = (band > 0)        ? &g_prog[img*NBANDS + band - 1] : (int*)0;
    int* rightProg = (band < NBANDS-1) ? &g_prog[img*NBANDS + band + 1] : (int*)0;
    const int base = *myProg;   // only this block ever writes myProg

    const float4 PINF = make_float4(BIGF,BIGF,BIGF,BIGF);
    const float4 NINF = make_float4(-BIGF,-BIGF,-BIGF,-BIGF);

    #pragma unroll 1
    for (int it = 0; it < NUM_ITER; it++) {
        // wait for neighbors to finish iteration it-1
        if (threadIdx.x == 0) {
            const int tgt = base + it;
            if (leftProg)  while (ld_acquire_gpu(leftProg)  < tgt) __nanosleep(32);
            if (rightProg) while (ld_acquire_gpu(rightProg) < tgt) __nanosleep(32);
        }
        __syncthreads();

        const float* __restrict__ in     = ((it & 1) ? g_imgB : g_imgA) + (size_t)img*HW;
        float*       __restrict__ outImg = ((it & 1) ? g_imgA : g_imgB) + (size_t)img*HW;

        float4 i0=PINF, i1=PINF, L0=PINF, L1=PINF, Rv0=PINF, Rv1=PINF;
        float4 hp=PINF; float hpL0=BIGF, hpL1=BIGF, hpR0=BIGF, hpR1=BIGF;
        float4 e1a=PINF, e1b=PINF; float e1aL=BIGF, e1bL=BIGF, e1aR=BIGF, e1bR=BIGF;
        float4 h1p=PINF; float h1pL=BIGF, h1pR=BIGF;
        float4 e2a=NINF, e2b=NINF; float e2aL=-BIGF, e2bL=-BIGF, e2aR=-BIGF, e2bR=-BIGF;

        const int rStart = R0row-3, rEnd = R0row+BH+2;   // BH+6 = 22 rows
        float4 nCur=PINF, nL=PINF, nR=PINF, nSk=make_float4(0,0,0,0);
        if (rStart >= 0 && rStart < H) {
            const float* p = in + rStart*W + colBase;
            nCur = *(const float4*)p;
            if (isL && !edgeL) nL = *(const float4*)(p - 4);
            if (isR && !edgeR) nR = *(const float4*)(p + 4);
        }

        #pragma unroll 2
        for (int t = 0; t < BH+6; t++) {
            const int r = rStart + t;
            float4 cur = nCur, Lc = nL, Rc = nR, skv = nSk;
            nCur = PINF; nL = PINF; nR = PINF;
            {
                int rn = r + 1;
                if (rn <= rEnd && (unsigned)rn < (unsigned)H) {
                    const float* p = in + rn*W + colBase;
                    nCur = *(const float4*)p;
                    if (isL && !edgeL) nL = *(const float4*)(p - 4);
                    if (isR && !edgeR) nR = *(const float4*)(p + 4);
                }
                if (rn >= R0row+3 && rn <= rEnd)
                    nSk = *(const float4*)(skel + (rn-3)*W + colBase);
            }
            // hmin3 of img row r (own cols + halo cols -2,-1,128,129)
            float xm1 = __shfl_up_sync(0xffffffffu, cur.w, 1); if (isL) xm1 = Lc.w;
            float xp1 = __shfl_down_sync(0xffffffffu, cur.x, 1); if (isR) xp1 = Rc.x;
            float4 hc;
            hc.x = f3min(xm1, cur.x, cur.y);
            hc.y = f3min(cur.x, cur.y, cur.z);
            hc.z = f3min(cur.y, cur.z, cur.w);
            hc.w = f3min(cur.z, cur.w, xp1);
            float hcL0 = f3min(Lc.y, Lc.z, Lc.w);
            float hcL1 = f3min(Lc.z, Lc.w, cur.x);
            float hcR0 = f3min(cur.w, Rc.x, Rc.y);
            float hcR1 = f3min(Rc.x, Rc.y, Rc.z);

            // e1 = erode(img) at row r-1 (feeds erode -> OOB = +INF)
            float4 e1n;
            e1n.x = fminf(f3min(i0.x,i1.x,cur.x), hp.x);
            e1n.y = fminf(f3min(i0.y,i1.y,cur.y), hp.y);
            e1n.z = fminf(f3min(i0.z,i1.z,cur.z), hp.z);
            e1n.w = fminf(f3min(i0.w,i1.w,cur.w), hp.w);
            float e1nL0 = fminf(f3min(L0.z,L1.z,Lc.z), hpL0);   // col -2
            float e1nL1 = fminf(f3min(L0.w,L1.w,Lc.w), hpL1);   // col -1
            float e1nR0 = fminf(f3min(Rv0.x,Rv1.x,Rc.x), hpR0); // col 128
            float e1nR1 = fminf(f3min(Rv0.y,Rv1.y,Rc.y), hpR1); // col 129
            {
                int k = r-1;
                if (k < 0 || k >= H) { e1n = PINF; e1nL0=e1nL1=e1nR0=e1nR1=BIGF; }
            }
            // hmin3 of e1 at row r-1 (cols -1..128)
            float em1 = __shfl_up_sync(0xffffffffu, e1n.w, 1); if (isL) em1 = e1nL1;
            float ep1 = __shfl_down_sync(0xffffffffu, e1n.x, 1); if (isR) ep1 = e1nR0;
            float4 h1c;
            h1c.x = f3min(em1, e1n.x, e1n.y);
            h1c.y = f3min(e1n.x, e1n.y, e1n.z);
            h1c.z = f3min(e1n.y, e1n.z, e1n.w);
            h1c.w = f3min(e1n.z, e1n.w, ep1);
            float h1cL = f3min(e1nL0, e1nL1, e1n.x);   // col -1
            float h1cR = f3min(e1n.w, e1nR0, e1nR1);   // col 128

            // e2 = erode(e1) at row r-2 (feeds dilate -> OOB = -INF)
            float4 e2n;
            e2n.x = fminf(f3min(e1a.x,e1b.x,e1n.x), h1p.x);
            e2n.y = fminf(f3min(e1a.y,e1b.y,e1n.y), h1p.y);
            e2n.z = fminf(f3min(e1a.z,e1b.z,e1n.z), h1p.z);
            e2n.w = fminf(f3min(e1a.w,e1b.w,e1n.w), h1p.w);
            float e2nL = fminf(f3min(e1aL,e1bL,e1nL1), h1pL);
            float e2nR = fminf(f3min(e1aR,e1bR,e1nR0), h1pR);
            {
                int j = r-2;
                if (j < 0 || j >= H) { e2n = NINF; e2nL = e2nR = -BIGF; }
            }
            if (edgeL) e2nL = -BIGF;
            if (edgeR) e2nR = -BIGF;

            // out row r-3: open = dilate3x3(e2); delta = relu(e1 - open); skel update
            if (t >= 6) {   // r >= R0row+3
                float4 mv;
                mv.x = f3max(e2a.x, e2b.x, e2n.x);
                mv.y = f3max(e2a.y, e2b.y, e2n.y);
                mv.z = f3max(e2a.z, e2b.z, e2n.z);
                mv.w = f3max(e2a.w, e2b.w, e2n.w);
                float mvL = f3max(e2aL, e2bL, e2nL);
                float mvR = f3max(e2aR, e2bR, e2nR);
                float mm1 = __shfl_up_sync(0xffffffffu, mv.w, 1); if (isL) mm1 = mvL;
                float mp1 = __shfl_down_sync(0xffffffffu, mv.x, 1); if (isR) mp1 = mvR;
                float4 open;
                open.x = f3max(mm1, mv.x, mv.y);
                open.y = f3max(mv.x, mv.y, mv.z);
                open.z = f3max(mv.y, mv.z, mv.w);
                open.w = f3max(mv.z, mv.w, mp1);
                int k2 = r-3;
                float4 ec = e1a;   // e1 row r-3 (oldest in window)
                float4 sk = skv;
                float d0 = fmaxf(ec.x - open.x, 0.f); sk.x += fmaxf(d0 - sk.x*d0, 0.f);
                float d1 = fmaxf(ec.y - open.y, 0.f); sk.y += fmaxf(d1 - sk.y*d1, 0.f);
                float d2 = fmaxf(ec.z - open.z, 0.f); sk.z += fmaxf(d2 - sk.z*d2, 0.f);
                float d3 = fmaxf(ec.w - open.w, 0.f); sk.w += fmaxf(d3 - sk.w*d3, 0.f);
                *(float4*)(skel + k2*W + colBase) = sk;
                *(float4*)(outImg + k2*W + colBase) = ec;
            }
            // rotate windows (renamed away under unroll)
            i0=i1; i1=cur; L0=L1; L1=Lc; Rv0=Rv1; Rv1=Rc;
            hp=hc; hpL0=hcL0; hpL1=hcL1; hpR0=hcR0; hpR1=hcR1;
            e1a=e1b; e1b=e1n; e1aL=e1bL; e1bL=e1nL1; e1aR=e1bR; e1bR=e1nR0;
            h1p=h1c; h1pL=h1cL; h1pR=h1cR;
            e2a=e2b; e2b=e2n; e2aL=e2bL; e2bL=e2nL; e2aR=e2bR; e2bR=e2nR;
        }

        // publish iteration completion
        __threadfence();
        __syncthreads();
        if (threadIdx.x == 0) st_release_gpu(myProg, base + it + 1);
    }
}

// ---------------------------------------------------------------------------
// endpoints (band sweep): ns = sum3x3(skel) + 9*center (zero pad);
// ep = exp(-(ns-11)^2)*center; partial sums (ep, ep*y, ep*x) per (img, band).
// ---------------------------------------------------------------------------
__global__ __launch_bounds__(128) void endpoint_kernel() {
    const int img = blockIdx.y;
    const int R0row = blockIdx.x * BH;
    const int lane = threadIdx.x & 31;
    const int colBase = ((threadIdx.x >> 5) << 7) + (lane << 2);
    const bool isL = (lane == 0), isR = (lane == 31);
    const bool edgeL = (colBase == 0), edgeR = (colBase == W-4);
    const float* __restrict__ sk = g_skel + (size_t)img*HW;

    const float4 Z = make_float4(0.f,0.f,0.f,0.f);
    float4 i0=Z, i1=Z; float L0w=0.f,L1w=0.f,R0x=0.f,R1x=0.f;
    float s0=0.f, sy=0.f, sx=0.f;

    const int rStart = R0row-1, rEnd = R0row+BH;    // BH+2 = 18 rows
    float4 nCur=Z; float nLw=0.f, nRx=0.f;
    if (rStart >= 0 && rStart < H) {
        const float* p = sk + rStart*W + colBase;
        nCur = *(const float4*)p;
        if (isL && !edgeL) nLw = p[-1];
        if (isR && !edgeR) nRx = p[4];
    }

    #pragma unroll 2
    for (int t = 0; t < BH+2; t++) {
        const int r = rStart + t;
        float4 cur = nCur; float Lcw = nLw, Rcx = nRx;
        nCur = Z; nLw = 0.f; nRx = 0.f;
        {
            int rn = r + 1;
            if (rn <= rEnd && (unsigned)rn < (unsigned)H) {
                const float* p = sk + rn*W + colBase;
                nCur = *(const float4*)p;
                if (isL && !edgeL) nLw = p[-1];
                if (isR && !edgeR) nRx = p[4];
            }
        }
        int k = r-1;
        if (k >= R0row && k < R0row+BH) {
            float4 vs;
            vs.x = i0.x + i1.x + cur.x;
            vs.y = i0.y + i1.y + cur.y;
            vs.z = i0.z + i1.z + cur.z;
            vs.w = i0.w + i1.w + cur.w;
            float vsL = L0w + L1w + Lcw;
            float vsR = R0x + R1x + Rcx;
            float sm1 = __shfl_up_sync(0xffffffffu, vs.w, 1); if (isL) sm1 = vsL;
            float sp1 = __shfl_down_sync(0xffffffffu, vs.x, 1); if (isR) sp1 = vsR;
            float ns0 = sm1 + vs.x + vs.y + 9.f*i1.x;
            float ns1 = vs.x + vs.y + vs.z + 9.f*i1.y;
            float ns2 = vs.y + vs.z + vs.w + 9.f*i1.z;
            float ns3 = vs.z + vs.w + sp1 + 9.f*i1.w;
            float d0 = ns0 - 11.f, d1 = ns1 - 11.f, d2 = ns2 - 11.f, d3 = ns3 - 11.f;
            float e0 = __expf(-d0*d0) * i1.x;
            float e1 = __expf(-d1*d1) * i1.y;
            float e2 = __expf(-d2*d2) * i1.z;
            float e3 = __expf(-d3*d3) * i1.w;
            float es = e0 + e1 + e2 + e3;
            s0 += es;
            sy += es * (float)k;
            sx += e0*(float)colBase + e1*(float)(colBase+1)
                + e2*(float)(colBase+2) + e3*(float)(colBase+3);
        }
        i0=i1; i1=cur; L0w=L1w; L1w=Lcw; R0x=R1x; R1x=Rcx;
    }

    __shared__ float s[3][128];
    s[0][threadIdx.x] = s0; s[1][threadIdx.x] = sy; s[2][threadIdx.x] = sx;
    __syncthreads();
    for (int off = 64; off > 0; off >>= 1) {
        if (threadIdx.x < off) {
            s[0][threadIdx.x] += s[0][threadIdx.x + off];
            s[1][threadIdx.x] += s[1][threadIdx.x + off];
            s[2][threadIdx.x] += s[2][threadIdx.x + off];
        }
        __syncthreads();
    }
    if (threadIdx.x == 0) {
        int o = (img*NBANDS + blockIdx.x)*3;
        g_epPart[o + 0] = s[0][0];
        g_epPart[o + 1] = s[1][0];
        g_epPart[o + 2] = s[2][0];
    }
}

// ---------------------------------------------------------------------------
// final: combine everything into the scalar loss.
// ---------------------------------------------------------------------------
__global__ __launch_bounds__(256) void final_kernel(float* __restrict__ out) {
    __shared__ float s[3][256];
    s[0][threadIdx.x] = g_dicePart[threadIdx.x*3 + 0];
    s[1][threadIdx.x] = g_dicePart[threadIdx.x*3 + 1];
    s[2][threadIdx.x] = g_dicePart[threadIdx.x*3 + 2];
    __syncthreads();
    for (int off = 128; off > 0; off >>= 1) {
        if (threadIdx.x < off) {
            s[0][threadIdx.x] += s[0][threadIdx.x + off];
            s[1][threadIdx.x] += s[1][threadIdx.x + off];
            s[2][threadIdx.x] += s[2][threadIdx.x + off];
        }
        __syncthreads();
    }
    __shared__ float S[NIMG], SY[NIMG], SX[NIMG];
    if (threadIdx.x < NIMG) {
        float t0 = 0.f, t1 = 0.f, t2 = 0.f;
        for (int bd = 0; bd < NBANDS; bd++) {
            int o = (threadIdx.x*NBANDS + bd)*3;
            t0 += g_epPart[o + 0];
            t1 += g_epPart[o + 1];
            t2 += g_epPart[o + 2];
        }
        S[threadIdx.x] = t0; SY[threadIdx.x] = t1; SX[threadIdx.x] = t2;
    }
    __syncthreads();
    if (threadIdx.x == 0) {
        float inter = s[0][0], sumT = s[1][0], sumP = s[2][0];
        float dice = 1.f - (2.f*inter + 1.f) / (sumT + sumP + 1.f);
        float distsum = 0.f, cntsum = 0.f;
        for (int b = 0; b < NB; b++) {
            float np = S[b], nt = S[NB + b];
            float tp = np + 1e-8f, tt = nt + 1e-8f;
            float ycp = SY[b] / tp,      xcp = SX[b] / tp;
            float yct = SY[NB+b] / tt,   xct = SX[NB+b] / tt;
            float dy = ycp - yct, dx = xcp - xct;
            distsum += sqrtf(dy*dy + dx*dx);
            cntsum  += fabsf(np - nt) / (np + nt + 1e-8f);
        }
        float diag = sqrtf((float)(H*H) + (float)(W*W));
        float distance_loss = (distsum / (float)NB) / (diag * 1.0f + 1e-8f);
        float count_penalty = cntsum / (float)NB;
        out[0] = 0.85f * dice + 0.15f * (distance_loss + count_penalty);
    }
}

// ---------------------------------------------------------------------------
extern "C" void kernel_launch(void* const* d_in, const int* in_sizes, int n_in,
                              void* d_out, int out_size) {
    const float* net = (const float*)d_in[0];
    const int*   yt  = (const int*)d_in[1];
    float* out = (float*)d_out;
    (void)in_sizes; (void)n_in; (void)out_size;

    prep_kernel<<<256, 256>>>(net, yt);

    dim3 grid(NBANDS, NIMG);
    sweep_init_kernel<<<grid, 128>>>();       // skel init; img stays in A
    sweep_persist_kernel<<<grid, 128>>>();    // ALL 40 iterations, one launch
    endpoint_kernel<<<grid, 128>>>();
    final_kernel<<<1, 256>>>(out);
}

// round 9
// speedup vs baseline: 1.1769x; 1.1769x over previous
#include <cuda_runtime.h>
#include <math.h>

#define H 512
#define W 512
#define HW (512*512)
#define NB 8          // batch
#define NIMG 16       // 8 pred + 8 true
#define NUM_ITER 40
#define BH 16
#define NBANDS (H/BH)   // 32
#define BIGF 3.0e38f

// ---- scratch (device globals; no allocation) ----
// g_skel stores q = 1 - skel  (multiplicative form: q *= (1 - delta))
__device__ float g_imgA[(size_t)NIMG*HW];
__device__ float g_imgB[(size_t)NIMG*HW];
__device__ float g_skel[(size_t)NIMG*HW];
__device__ float g_dicePart[256*3];           // [block][inter,sumT,sumP]
__device__ float g_epPart[NIMG*NBANDS*3];     // [img][band][s,sy,sx]

__device__ __forceinline__ float f3min(float a,float b,float c){return fminf(fminf(a,b),c);}
__device__ __forceinline__ float f3max(float a,float b,float c){return fmaxf(fmaxf(a,b),c);}

// ---------------------------------------------------------------------------
// prep: prob = softmax(net)[:,1] = sigmoid(x1-x0); true->float; dice partials.
// ---------------------------------------------------------------------------
__global__ void prep_kernel(const float* __restrict__ net, const int* __restrict__ yt) {
    int tid = blockIdx.x * 256 + threadIdx.x;
    float inter = 0.f, st = 0.f, sp = 0.f;
    for (int idx = tid; idx < NB*HW; idx += 256*256) {
        int b = idx / HW;
        int p = idx - b*HW;
        float x0 = net[(size_t)b*2*HW + p];
        float x1 = net[(size_t)b*2*HW + HW + p];
        float prob = 1.f / (1.f + __expf(x0 - x1));
        float t = (float)yt[idx];
        g_imgA[(size_t)b*HW + p] = prob;
        g_imgA[(size_t)(NB + b)*HW + p] = t;
        inter += t * prob;
        st += t;
        sp += prob;
    }
    __shared__ float s[3][256];
    s[0][threadIdx.x] = inter; s[1][threadIdx.x] = st; s[2][threadIdx.x] = sp;
    __syncthreads();
    for (int off = 128; off > 0; off >>= 1) {
        if (threadIdx.x < off) {
            s[0][threadIdx.x] += s[0][threadIdx.x + off];
            s[1][threadIdx.x] += s[1][threadIdx.x + off];
            s[2][threadIdx.x] += s[2][threadIdx.x + off];
        }
        __syncthreads();
    }
    if (threadIdx.x == 0) {
        g_dicePart[blockIdx.x*3 + 0] = s[0][0];
        g_dicePart[blockIdx.x*3 + 1] = s[1][0];
        g_dicePart[blockIdx.x*3 + 2] = s[2][0];
    }
}

// ---------------------------------------------------------------------------
// INIT sweep: q = 1 - relu(img - dilate3x3(erode(img))).  (single launch)
// ---------------------------------------------------------------------------
__global__ __launch_bounds__(128) void sweep_init_kernel() {
    const int img = blockIdx.y;
    const int R0row = blockIdx.x * BH;
    const int lane = threadIdx.x & 31;
    const int colBase = ((threadIdx.x >> 5) << 7) + (lane << 2);
    const bool isL = (lane == 0), isR = (lane == 31);
    const bool edgeL = (colBase == 0), edgeR = (colBase == W-4);
    const float* __restrict__ in = g_imgA + (size_t)img*HW;
    float* __restrict__ skel = g_skel + (size_t)img*HW;

    const float4 PINF = make_float4(BIGF,BIGF,BIGF,BIGF);
    float4 i0=PINF, i1=PINF, L0=PINF, L1=PINF, Rv0=PINF, Rv1=PINF;
    float4 hp=PINF; float hpL1=BIGF, hpR0=BIGF;
    float4 e1a=make_float4(-BIGF,-BIGF,-BIGF,-BIGF), e1b=e1a;
    float e1aL=-BIGF, e1bL=-BIGF, e1aR=-BIGF, e1bR=-BIGF;

    const int rStart = R0row-2, rEnd = R0row+BH+1;   // BH+4 = 20 rows
    float4 nCur=PINF, nL=PINF, nR=PINF;
    if (rStart >= 0 && rStart < H) {
        const float* p = in + rStart*W + colBase;
        nCur = *(const float4*)p;
        if (isL && !edgeL) nL = *(const float4*)(p - 4);
        if (isR && !edgeR) nR = *(const float4*)(p + 4);
    }

    #pragma unroll 2
    for (int t = 0; t < BH+4; t++) {
        const int r = rStart + t;
        float4 cur = nCur, Lc = nL, Rc = nR;
        nCur = PINF; nL = PINF; nR = PINF;
        {
            int rn = r + 1;
            if (rn <= rEnd && (unsigned)rn < (unsigned)H) {
                const float* p = in + rn*W + colBase;
                nCur = *(const float4*)p;
                if (isL && !edgeL) nL = *(const float4*)(p - 4);
                if (isR && !edgeR) nR = *(const float4*)(p + 4);
            }
        }
        float xm1 = __shfl_up_sync(0xffffffffu, cur.w, 1); if (isL) xm1 = Lc.w;
        float xp1 = __shfl_down_sync(0xffffffffu, cur.x, 1); if (isR) xp1 = Rc.x;
        float4 hc;
        hc.x = f3min(xm1, cur.x, cur.y);
        hc.y = f3min(cur.x, cur.y, cur.z);
        hc.z = f3min(cur.y, cur.z, cur.w);
        hc.w = f3min(cur.z, cur.w, xp1);
        float hcL1 = f3min(Lc.z, Lc.w, cur.x);
        float hcR0 = f3min(cur.w, Rc.x, Rc.y);

        float4 e1n;
        e1n.x = fminf(f3min(i0.x,i1.x,cur.x), hp.x);
        e1n.y = fminf(f3min(i0.y,i1.y,cur.y), hp.y);
        e1n.z = fminf(f3min(i0.z,i1.z,cur.z), hp.z);
        e1n.w = fminf(f3min(i0.w,i1.w,cur.w), hp.w);
        float e1nL = fminf(f3min(L0.w,L1.w,Lc.w), hpL1);
        float e1nR = fminf(f3min(Rv0.x,Rv1.x,Rc.x), hpR0);
        {
            int k = r-1;
            if (k < 0 || k >= H) {
                e1n = make_float4(-BIGF,-BIGF,-BIGF,-BIGF);
                e1nL = e1nR = -BIGF;
            }
        }
        if (edgeL) e1nL = -BIGF;
        if (edgeR) e1nR = -BIGF;

        if (t >= 4) {   // r >= R0row+2
            float4 mv;
            mv.x = f3max(e1a.x, e1b.x, e1n.x);
            mv.y = f3max(e1a.y, e1b.y, e1n.y);
            mv.z = f3max(e1a.z, e1b.z, e1n.z);
            mv.w = f3max(e1a.w, e1b.w, e1n.w);
            float mvL = f3max(e1aL, e1bL, e1nL);
            float mvR = f3max(e1aR, e1bR, e1nR);
            float mm1 = __shfl_up_sync(0xffffffffu, mv.w, 1); if (isL) mm1 = mvL;
            float mp1 = __shfl_down_sync(0xffffffffu, mv.x, 1); if (isR) mp1 = mvR;
            float4 open;
            open.x = f3max(mm1, mv.x, mv.y);
            open.y = f3max(mv.x, mv.y, mv.z);
            open.z = f3max(mv.y, mv.z, mv.w);
            open.w = f3max(mv.z, mv.w, mp1);
            int k2 = r-2;
            float4 s;
            s.x = 1.f - fmaxf(i0.x - open.x, 0.f);
            s.y = 1.f - fmaxf(i0.y - open.y, 0.f);
            s.z = 1.f - fmaxf(i0.z - open.z, 0.f);
            s.w = 1.f - fmaxf(i0.w - open.w, 0.f);
            *(float4*)(skel + k2*W + colBase) = s;
        }
        i0=i1; i1=cur; L0=L1; L1=Lc; Rv0=Rv1; Rv1=Rc;
        hp=hc; hpL1=hcL1; hpR0=hcR0;
        e1a=e1b; e1b=e1n; e1aL=e1bL; e1bL=e1nL; e1aR=e1bR; e1bR=e1nR;
    }
}

// ---------------------------------------------------------------------------
// STEP body, templated on BOUNDARY. Interior bands (1..30) have all touched
// rows in [11,499] -> every row check removed, all loads unconditional.
// q update: q *= (1 - delta)  (one FFMA per pixel).
// ---------------------------------------------------------------------------
template<bool BOUNDARY>
__device__ __forceinline__ void step_body(
    const float* __restrict__ in, float* __restrict__ outImg,
    float* __restrict__ skel, int R0row, int colBase,
    bool isL, bool isR, bool edgeL, bool edgeR)
{
    const float4 PINF = make_float4(BIGF,BIGF,BIGF,BIGF);
    const float4 NINF = make_float4(-BIGF,-BIGF,-BIGF,-BIGF);

    float4 i0=PINF, i1=PINF, L0=PINF, L1=PINF, Rv0=PINF, Rv1=PINF;
    float4 hp=PINF; float hpL0=BIGF, hpL1=BIGF, hpR0=BIGF, hpR1=BIGF;
    float4 e1a=PINF, e1b=PINF; float e1aL=BIGF, e1bL=BIGF, e1aR=BIGF, e1bR=BIGF;
    float4 h1p=PINF; float h1pL=BIGF, h1pR=BIGF;
    float4 e2a=NINF, e2b=NINF; float e2aL=-BIGF, e2bL=-BIGF, e2aR=-BIGF, e2bR=-BIGF;

    const int rStart = R0row-3, rEnd = R0row+BH+2;   // BH+6 = 22 rows
    float4 nCur=PINF, nL=PINF, nR=PINF, nSk=make_float4(0,0,0,0);
    if (!BOUNDARY || (rStart >= 0 && rStart < H)) {
        const float* p = in + rStart*W + colBase;
        nCur = *(const float4*)p;
        if (isL && !edgeL) nL = *(const float4*)(p - 4);
        if (isR && !edgeR) nR = *(const float4*)(p + 4);
    }

    #pragma unroll 2
    for (int t = 0; t < BH+6; t++) {
        const int r = rStart + t;
        float4 cur = nCur, Lc = nL, Rc = nR, skv = nSk;
        {
            int rn = r + 1;
            if (BOUNDARY) {
                nCur = PINF; nL = PINF; nR = PINF;
                if (rn <= rEnd && (unsigned)rn < (unsigned)H) {
                    const float* p = in + rn*W + colBase;
                    nCur = *(const float4*)p;
                    if (isL && !edgeL) nL = *(const float4*)(p - 4);
                    if (isR && !edgeR) nR = *(const float4*)(p + 4);
                }
                if (rn >= R0row+3 && rn <= rEnd)
                    nSk = *(const float4*)(skel + (rn-3)*W + colBase);
            } else {
                // all rows rn in [rStart+1, rEnd+1] subset [12, 500): valid.
                const float* p = in + rn*W + colBase;
                nCur = *(const float4*)p;
                nL = PINF; nR = PINF;
                if (isL && !edgeL) nL = *(const float4*)(p - 4);
                if (isR && !edgeR) nR = *(const float4*)(p + 4);
                // skel row rn-3 in [R0row-5, R0row+BH] subset [11, 496]: valid.
                nSk = *(const float4*)(skel + (rn-3)*W + colBase);
            }
        }
        // hmin3 of img row r (own cols + halo cols -2,-1,128,129)
        float xm1 = __shfl_up_sync(0xffffffffu, cur.w, 1); if (isL) xm1 = Lc.w;
        float xp1 = __shfl_down_sync(0xffffffffu, cur.x, 1); if (isR) xp1 = Rc.x;
        float4 hc;
        hc.x = f3min(xm1, cur.x, cur.y);
        hc.y = f3min(cur.x, cur.y, cur.z);
        hc.z = f3min(cur.y, cur.z, cur.w);
        hc.w = f3min(cur.z, cur.w, xp1);
        float hcL0 = f3min(Lc.y, Lc.z, Lc.w);
        float hcL1 = f3min(Lc.z, Lc.w, cur.x);
        float hcR0 = f3min(cur.w, Rc.x, Rc.y);
        float hcR1 = f3min(Rc.x, Rc.y, Rc.z);

        // e1 = erode(img) at row r-1 (feeds erode -> OOB = +INF)
        float4 e1n;
        e1n.x = fminf(f3min(i0.x,i1.x,cur.x), hp.x);
        e1n.y = fminf(f3min(i0.y,i1.y,cur.y), hp.y);
        e1n.z = fminf(f3min(i0.z,i1.z,cur.z), hp.z);
        e1n.w = fminf(f3min(i0.w,i1.w,cur.w), hp.w);
        float e1nL0 = fminf(f3min(L0.z,L1.z,Lc.z), hpL0);   // col -2
        float e1nL1 = fminf(f3min(L0.w,L1.w,Lc.w), hpL1);   // col -1
        float e1nR0 = fminf(f3min(Rv0.x,Rv1.x,Rc.x), hpR0); // col 128
        float e1nR1 = fminf(f3min(Rv0.y,Rv1.y,Rc.y), hpR1); // col 129
        if (BOUNDARY) {
            int k = r-1;
            if (k < 0 || k >= H) { e1n = PINF; e1nL0=e1nL1=e1nR0=e1nR1=BIGF; }
        }
        // hmin3 of e1 at row r-1 (cols -1..128)
        float em1 = __shfl_up_sync(0xffffffffu, e1n.w, 1); if (isL) em1 = e1nL1;
        float ep1 = __shfl_down_sync(0xffffffffu, e1n.x, 1); if (isR) ep1 = e1nR0;
        float4 h1c;
        h1c.x = f3min(em1, e1n.x, e1n.y);
        h1c.y = f3min(e1n.x, e1n.y, e1n.z);
        h1c.z = f3min(e1n.y, e1n.z, e1n.w);
        h1c.w = f3min(e1n.z, e1n.w, ep1);
        float h1cL = f3min(e1nL0, e1nL1, e1n.x);   // col -1
        float h1cR = f3min(e1n.w, e1nR0, e1nR1);   // col 128

        // e2 = erode(e1) at row r-2 (feeds dilate -> OOB = -INF)
        float4 e2n;
        e2n.x = fminf(f3min(e1a.x,e1b.x,e1n.x), h1p.x);
        e2n.y = fminf(f3min(e1a.y,e1b.y,e1n.y), h1p.y);
        e2n.z = fminf(f3min(e1a.z,e1b.z,e1n.z), h1p.z);
        e2n.w = fminf(f3min(e1a.w,e1b.w,e1n.w), h1p.w);
        float e2nL = fminf(f3min(e1aL,e1bL,e1nL1), h1pL);
        float e2nR = fminf(f3min(e1aR,e1bR,e1nR0), h1pR);
        if (BOUNDARY) {
            int j = r-2;
            if (j < 0 || j >= H) { e2n = NINF; e2nL = e2nR = -BIGF; }
        }
        if (edgeL) e2nL = -BIGF;
        if (edgeR) e2nR = -BIGF;

        // out row r-3: open = dilate3x3(e2); delta = relu(e1 - open); q *= (1-delta)
        if (t >= 6) {   // r >= R0row+3
            float4 mv;
            mv.x = f3max(e2a.x, e2b.x, e2n.x);
            mv.y = f3max(e2a.y, e2b.y, e2n.y);
            mv.z = f3max(e2a.z, e2b.z, e2n.z);
            mv.w = f3max(e2a.w, e2b.w, e2n.w);
            float mvL = f3max(e2aL, e2bL, e2nL);
            float mvR = f3max(e2aR, e2bR, e2nR);
            float mm1 = __shfl_up_sync(0xffffffffu, mv.w, 1); if (isL) mm1 = mvL;
            float mp1 = __shfl_down_sync(0xffffffffu, mv.x, 1); if (isR) mp1 = mvR;
            float4 open;
            open.x = f3max(mm1, mv.x, mv.y);
            open.y = f3max(mv.x, mv.y, mv.z);
            open.z = f3max(mv.y, mv.z, mv.w);
            open.w = f3max(mv.z, mv.w, mp1);
            int k2 = r-3;
            float4 ec = e1a;   // e1 row r-3 (oldest in window)
            float4 q = skv;
            float d0 = fmaxf(ec.x - open.x, 0.f); q.x -= q.x*d0;
            float d1 = fmaxf(ec.y - open.y, 0.f); q.y -= q.y*d1;
            float d2 = fmaxf(ec.z - open.z, 0.f); q.z -= q.z*d2;
            float d3 = fmaxf(ec.w - open.w, 0.f); q.w -= q.w*d3;
            *(float4*)(skel + k2*W + colBase) = q;
            *(float4*)(outImg + k2*W + colBase) = ec;
        }
        // rotate windows (renamed away under unroll)
        i0=i1; i1=cur; L0=L1; L1=Lc; Rv0=Rv1; Rv1=Rc;
        hp=hc; hpL0=hcL0; hpL1=hcL1; hpR0=hcR0; hpR1=hcR1;
        e1a=e1b; e1b=e1n; e1aL=e1bL; e1bL=e1nL1; e1aR=e1bR; e1bR=e1nR0;
        h1p=h1c; h1pL=h1cL; h1pR=h1cR;
        e2a=e2b; e2b=e2n; e2aL=e2bL; e2bL=e2nL; e2aR=e2bR; e2bR=e2nR;
    }
}

__global__ __launch_bounds__(128) void sweep_step_kernel(int bufsel) {
    const int img = blockIdx.y;
    const int band = blockIdx.x;
    const int R0row = band * BH;
    const int lane = threadIdx.x & 31;
    const int colBase = ((threadIdx.x >> 5) << 7) + (lane << 2);
    const bool isL = (lane == 0), isR = (lane == 31);
    const bool edgeL = (colBase == 0), edgeR = (colBase == W-4);
    const float* __restrict__ in     = (bufsel ? g_imgB : g_imgA) + (size_t)img*HW;
    float*       __restrict__ outImg = (bufsel ? g_imgA : g_imgB) + (size_t)img*HW;
    float*       __restrict__ skel   = g_skel + (size_t)img*HW;

    if (band == 0 || band == NBANDS-1)
        step_body<true >(in, outImg, skel, R0row, colBase, isL, isR, edgeL, edgeR);
    else
        step_body<false>(in, outImg, skel, R0row, colBase, isL, isR, edgeL, edgeR);
}

// ---------------------------------------------------------------------------
// endpoints: skel = 1 - q on load; ns = sum3x3(skel) + 9*center (zero pad);
// ep = exp(-(ns-11)^2)*center; partial sums per (img, band).
// ---------------------------------------------------------------------------
__global__ __launch_bounds__(128) void endpoint_kernel() {
    const int img = blockIdx.y;
    const int R0row = blockIdx.x * BH;
    const int lane = threadIdx.x & 31;
    const int colBase = ((threadIdx.x >> 5) << 7) + (lane << 2);
    const bool isL = (lane == 0), isR = (lane == 31);
    const bool edgeL = (colBase == 0), edgeR = (colBase == W-4);
    const float* __restrict__ sk = g_skel + (size_t)img*HW;

    const float4 Z = make_float4(0.f,0.f,0.f,0.f);
    float4 i0=Z, i1=Z; float L0w=0.f,L1w=0.f,R0x=0.f,R1x=0.f;
    float s0=0.f, sy=0.f, sx=0.f;

    const int rStart = R0row-1, rEnd = R0row+BH;    // BH+2 = 18 rows
    float4 nCur=Z; float nLw=0.f, nRx=0.f;
    if (rStart >= 0 && rStart < H) {
        const float* p = sk + rStart*W + colBase;
        float4 q = *(const float4*)p;
        nCur = make_float4(1.f-q.x, 1.f-q.y, 1.f-q.z, 1.f-q.w);
        if (isL && !edgeL) nLw = 1.f - p[-1];
        if (isR && !edgeR) nRx = 1.f - p[4];
    }

    #pragma unroll 2
    for (int t = 0; t < BH+2; t++) {
        const int r = rStart + t;
        float4 cur = nCur; float Lcw = nLw, Rcx = nRx;
        nCur = Z; nLw = 0.f; nRx = 0.f;
        {
            int rn = r + 1;
            if (rn <= rEnd && (unsigned)rn < (unsigned)H) {
                const float* p = sk + rn*W + colBase;
                float4 q = *(const float4*)p;
                nCur = make_float4(1.f-q.x, 1.f-q.y, 1.f-q.z, 1.f-q.w);
                if (isL && !edgeL) nLw = 1.f - p[-1];
                if (isR && !edgeR) nRx = 1.f - p[4];
            }
        }
        int k = r-1;
        if (k >= R0row && k < R0row+BH) {
            float4 vs;
            vs.x = i0.x + i1.x + cur.x;
            vs.y = i0.y + i1.y + cur.y;
            vs.z = i0.z + i1.z + cur.z;
            vs.w = i0.w + i1.w + cur.w;
            float vsL = L0w + L1w + Lcw;
            float vsR = R0x + R1x + Rcx;
            float sm1 = __shfl_up_sync(0xffffffffu, vs.w, 1); if (isL) sm1 = vsL;
            float sp1 = __shfl_down_sync(0xffffffffu, vs.x, 1); if (isR) sp1 = vsR;
            float ns0 = sm1 + vs.x + vs.y + 9.f*i1.x;
            float ns1 = vs.x + vs.y + vs.z + 9.f*i1.y;
            float ns2 = vs.y + vs.z + vs.w + 9.f*i1.z;
            float ns3 = vs.z + vs.w + sp1 + 9.f*i1.w;
            float d0 = ns0 - 11.f, d1 = ns1 - 11.f, d2 = ns2 - 11.f, d3 = ns3 - 11.f;
            float e0 = __expf(-d0*d0) * i1.x;
            float e1 = __expf(-d1*d1) * i1.y;
            float e2 = __expf(-d2*d2) * i1.z;
            float e3 = __expf(-d3*d3) * i1.w;
            float es = e0 + e1 + e2 + e3;
            s0 += es;
            sy += es * (float)k;
            sx += e0*(float)colBase + e1*(float)(colBase+1)
                + e2*(float)(colBase+2) + e3*(float)(colBase+3);
        }
        i0=i1; i1=cur; L0w=L1w; L1w=Lcw; R0x=R1x; R1x=Rcx;
    }

    __shared__ float s[3][128];
    s[0][threadIdx.x] = s0; s[1][threadIdx.x] = sy; s[2][threadIdx.x] = sx;
    __syncthreads();
    for (int off = 64; off > 0; off >>= 1) {
        if (threadIdx.x < off) {
            s[0][threadIdx.x] += s[0][threadIdx.x + off];
            s[1][threadIdx.x] += s[1][threadIdx.x + off];
            s[2][threadIdx.x] += s[2][threadIdx.x + off];
        }
        __syncthreads();
    }
    if (threadIdx.x == 0) {
        int o = (img*NBANDS + blockIdx.x)*3;
        g_epPart[o + 0] = s[0][0];
        g_epPart[o + 1] = s[1][0];
        g_epPart[o + 2] = s[2][0];
    }
}

// ---------------------------------------------------------------------------
// final: combine everything into the scalar loss.
// ---------------------------------------------------------------------------
__global__ __launch_bounds__(256) void final_kernel(float* __restrict__ out) {
    __shared__ float s[3][256];
    s[0][threadIdx.x] = g_dicePart[threadIdx.x*3 + 0];
    s[1][threadIdx.x] = g_dicePart[threadIdx.x*3 + 1];
    s[2][threadIdx.x] = g_dicePart[threadIdx.x*3 + 2];
    __syncthreads();
    for (int off = 128; off > 0; off >>= 1) {
        if (threadIdx.x < off) {
            s[0][threadIdx.x] += s[0][threadIdx.x + off];
            s[1][threadIdx.x] += s[1][threadIdx.x + off];
            s[2][threadIdx.x] += s[2][threadIdx.x + off];
        }
        __syncthreads();
    }
    __shared__ float S[NIMG], SY[NIMG], SX[NIMG];
    if (threadIdx.x < NIMG) {
        float t0 = 0.f, t1 = 0.f, t2 = 0.f;
        for (int bd = 0; bd < NBANDS; bd++) {
            int o = (threadIdx.x*NBANDS + bd)*3;
            t0 += g_epPart[o + 0];
            t1 += g_epPart[o + 1];
            t2 += g_epPart[o + 2];
        }
        S[threadIdx.x] = t0; SY[threadIdx.x] = t1; SX[threadIdx.x] = t2;
    }
    __syncthreads();
    if (threadIdx.x == 0) {
        float inter = s[0][0], sumT = s[1][0], sumP = s[2][0];
        float dice = 1.f - (2.f*inter + 1.f) / (sumT + sumP + 1.f);
        float distsum = 0.f, cntsum = 0.f;
        for (int b = 0; b < NB; b++) {
            float np = S[b], nt = S[NB + b];
            float tp = np + 1e-8f, tt = nt + 1e-8f;
            float ycp = SY[b] / tp,      xcp = SX[b] / tp;
            float yct = SY[NB+b] / tt,   xct = SX[NB+b] / tt;
            float dy = ycp - yct, dx = xcp - xct;
            distsum += sqrtf(dy*dy + dx*dx);
            cntsum  += fabsf(np - nt) / (np + nt + 1e-8f);
        }
        float diag = sqrtf((float)(H*H) + (float)(W*W));
        float distance_loss = (distsum / (float)NB) / (diag * 1.0f + 1e-8f);
        float count_penalty = cntsum / (float)NB;
        out[0] = 0.85f * dice + 0.15f * (distance_loss + count_penalty);
    }
}

// ---------------------------------------------------------------------------
extern "C" void kernel_launch(void* const* d_in, const int* in_sizes, int n_in,
                              void* d_out, int out_size) {
    const float* net = (const float*)d_in[0];
    const int*   yt  = (const int*)d_in[1];
    float* out = (float*)d_out;
    (void)in_sizes; (void)n_in; (void)out_size;

    prep_kernel<<<256, 256>>>(net, yt);

    dim3 grid(NBANDS, NIMG);
    sweep_init_kernel<<<grid, 128>>>();             // q init; img stays in A
    for (int i = 0; i < NUM_ITER; i++)
        sweep_step_kernel<<<grid, 128>>>(i & 1);    // ping-pong A<->B
    endpoint_kernel<<<grid, 128>>>();
    final_kernel<<<1, 256>>>(out);
}